// round 3
// baseline (speedup 1.0000x reference)
#include <cuda_runtime.h>
#include <cstdint>

#define BATCH 32
#define DIM   256
#define HW    56
#define SP    (HW*HW)        // 3136
#define PW    7
#define PP    49
#define DD    3
#define N1    8
#define N2    8
#define NWIN  64
#define HEADS 8
#define DH    32
#define INNER 256
#define QKV_N 768
#define M_TOTAL (BATCH*NWIN*PP)   // 100352

// scratch (allowed: __device__ globals, no runtime alloc)
__device__ float g_qkv[(size_t)M_TOTAL * QKV_N];   // ~308 MB
__device__ float g_att[(size_t)M_TOTAL * INNER];   // ~103 MB

// row index (b, window, token) -> x/out base offset: b*DIM*SP + hh*HW + ww
__device__ __forceinline__ int row_to_off(int r) {
    int bi  = r / (NWIN * PP);
    int rem = r % (NWIN * PP);
    int w   = rem / PP;
    int t   = rem % PP;
    int n1i = w / N2, n2i = w % N2;
    int py  = t / PW, px  = t % PW;
    int hh  = (n1i * PW + py + DD) % HW;
    int ww  = (n2i * PW + px + DD) % HW;
    return bi * DIM * SP + hh * HW + ww;
}

// ---------------------------------------------------------------------------
// Kernel 1: qkv = window(roll(x)) @ w_qkv
// 64x64 tile, K-chunk 16, 256 threads, 4x4 micro-tile
// ---------------------------------------------------------------------------
__global__ void __launch_bounds__(256) qkv_gemm(const float* __restrict__ x,
                                                const float* __restrict__ wqkv) {
    __shared__ float As[16][64];
    __shared__ float Bs[16][64];
    __shared__ int   rowoff[64];

    const int m0  = blockIdx.x * 64;
    const int n0  = blockIdx.y * 64;
    const int tid = threadIdx.x;

    if (tid < 64) rowoff[tid] = row_to_off(m0 + tid);
    __syncthreads();

    const int tr = (tid % 16) * 4;
    const int tc = (tid / 16) * 4;
    const int lr = tid % 64;
    const int lk = tid / 64;   // 0..3

    float acc[4][4] = {};

    for (int k0 = 0; k0 < DIM; k0 += 16) {
        #pragma unroll
        for (int kk = 0; kk < 16; kk += 4) {
            As[kk + lk][lr] = x[rowoff[lr] + (k0 + kk + lk) * SP];
            Bs[kk + lk][lr] = wqkv[(k0 + kk + lk) * QKV_N + n0 + lr];
        }
        __syncthreads();
        #pragma unroll
        for (int k = 0; k < 16; k++) {
            float4 a = *(const float4*)&As[k][tr];
            float4 b = *(const float4*)&Bs[k][tc];
            acc[0][0] += a.x * b.x; acc[0][1] += a.x * b.y; acc[0][2] += a.x * b.z; acc[0][3] += a.x * b.w;
            acc[1][0] += a.y * b.x; acc[1][1] += a.y * b.y; acc[1][2] += a.y * b.z; acc[1][3] += a.y * b.w;
            acc[2][0] += a.z * b.x; acc[2][1] += a.z * b.y; acc[2][2] += a.z * b.z; acc[2][3] += a.z * b.w;
            acc[3][0] += a.w * b.x; acc[3][1] += a.w * b.y; acc[3][2] += a.w * b.z; acc[3][3] += a.w * b.w;
        }
        __syncthreads();
    }

    #pragma unroll
    for (int ii = 0; ii < 4; ii++) {
        float4 v = make_float4(acc[ii][0], acc[ii][1], acc[ii][2], acc[ii][3]);
        *(float4*)&g_qkv[(size_t)(m0 + tr + ii) * QKV_N + n0 + tc] = v;
    }
}

// ---------------------------------------------------------------------------
// Kernel 2: per (b, window, head) attention. Writes attn to d_out tail,
// writes attn@v to g_att.
// ---------------------------------------------------------------------------
__global__ void __launch_bounds__(128) attn_kernel(const float* __restrict__ pos,
                                                   float* __restrict__ attn_out) {
    const int bid  = blockIdx.x;                // bi*NWIN*HEADS + w*HEADS + head
    const int head = bid % HEADS;
    const int bw   = bid / HEADS;
    const int w    = bw % NWIN;
    const int bi   = bw / NWIN;
    const int tid  = threadIdx.x;

    __shared__ float q[PP][DH], kk[PP][DH], v[PP][DH];
    __shared__ float dots[PP][PP + 1];
    __shared__ float poss[169];

    const float* base = g_qkv + (size_t)(bi * NWIN + w) * PP * QKV_N + head * DH;
    for (int idx = tid; idx < PP * DH; idx += 128) {
        int t = idx / DH, d = idx % DH;
        const float* rowp = base + (size_t)t * QKV_N + d;
        q[t][d]  = rowp[0];
        kk[t][d] = rowp[INNER];
        v[t][d]  = rowp[2 * INNER];
    }
    for (int idx = tid; idx < 169; idx += 128) poss[idx] = pos[idx];  // FIX: full table
    __syncthreads();

    const bool m_ul = (w >= NWIN - N2);                       // windows 56..63
    const bool m_lr = (w >= NWIN - N1 - 1) && ((w - (NWIN - N1 - 1)) % N1 == 0); // {55,63}
    const float NEG = -1e30f;
    const float scale = 0.17677669529663687f;  // 1/sqrt(32)

    for (int idx = tid; idx < PP * PP; idx += 128) {
        int i = idx / PP, j = idx % PP;
        float s = 0.f;
        #pragma unroll
        for (int d = 0; d < DH; d++) s += q[i][d] * kk[j][d];
        s *= scale;
        int iy = i / PW, ix = i % PW, jy = j / PW, jx = j % PW;
        s += poss[(jy - iy + 6) * 13 + (jx - ix + 6)];
        if (m_ul && ((iy >= 4) != (jy >= 4))) s = NEG;
        if (m_lr && ((ix >= 4) != (jx >= 4))) s = NEG;
        dots[i][j] = s;
    }
    __syncthreads();

    if (tid < PP) {
        int i = tid;
        float m = -3.4e38f;
        #pragma unroll
        for (int j = 0; j < PP; j++) m = fmaxf(m, dots[i][j]);
        float sum = 0.f;
        #pragma unroll
        for (int j = 0; j < PP; j++) {
            float e = __expf(dots[i][j] - m);
            dots[i][j] = e;
            sum += e;
        }
        float inv = 1.0f / sum;
        #pragma unroll
        for (int j = 0; j < PP; j++) dots[i][j] *= inv;
    }
    __syncthreads();

    float* ao = attn_out + (size_t)bid * (PP * PP);
    for (int idx = tid; idx < PP * PP; idx += 128)
        ao[idx] = dots[idx / PP][idx % PP];

    float* ob = g_att + (size_t)(bi * NWIN + w) * PP * INNER + head * DH;
    for (int idx = tid; idx < PP * DH; idx += 128) {
        int i = idx / DH, d = idx % DH;
        float s = 0.f;
        #pragma unroll
        for (int j = 0; j < PP; j++) s += dots[i][j] * v[j][d];
        ob[(size_t)i * INNER + d] = s;
    }
}

// ---------------------------------------------------------------------------
// Kernel 3: out = g_att @ w_out + b_out, scattered back through inverse
// window transform + roll(+3,+3)
// ---------------------------------------------------------------------------
__global__ void __launch_bounds__(256) out_gemm(const float* __restrict__ wout,
                                                const float* __restrict__ bout,
                                                float* __restrict__ out) {
    __shared__ float As[16][64];
    __shared__ float Bs[16][64];
    __shared__ int   rowoff[64];

    const int m0  = blockIdx.x * 64;
    const int n0  = blockIdx.y * 64;
    const int tid = threadIdx.x;

    if (tid < 64) rowoff[tid] = row_to_off(m0 + tid);
    __syncthreads();

    const int tr = (tid % 16) * 4;
    const int tc = (tid / 16) * 4;
    const int lr = tid % 64;
    const int lk = tid / 64;

    float acc[4][4] = {};

    for (int k0 = 0; k0 < INNER; k0 += 16) {
        #pragma unroll
        for (int kk = 0; kk < 16; kk += 4) {
            As[kk + lk][lr] = g_att[(size_t)(m0 + lr) * INNER + k0 + kk + lk];
            Bs[kk + lk][lr] = wout[(k0 + kk + lk) * DIM + n0 + lr];
        }
        __syncthreads();
        #pragma unroll
        for (int k = 0; k < 16; k++) {
            float4 a = *(const float4*)&As[k][tr];
            float4 b = *(const float4*)&Bs[k][tc];
            acc[0][0] += a.x * b.x; acc[0][1] += a.x * b.y; acc[0][2] += a.x * b.z; acc[0][3] += a.x * b.w;
            acc[1][0] += a.y * b.x; acc[1][1] += a.y * b.y; acc[1][2] += a.y * b.z; acc[1][3] += a.y * b.w;
            acc[2][0] += a.z * b.x; acc[2][1] += a.z * b.y; acc[2][2] += a.z * b.z; acc[2][3] += a.z * b.w;
            acc[3][0] += a.w * b.x; acc[3][1] += a.w * b.y; acc[3][2] += a.w * b.z; acc[3][3] += a.w * b.w;
        }
        __syncthreads();
    }

    #pragma unroll
    for (int ii = 0; ii < 4; ii++) {
        int ro = rowoff[tr + ii];
        #pragma unroll
        for (int jj = 0; jj < 4; jj++) {
            int c = n0 + tc + jj;
            out[ro + c * SP] = acc[ii][jj] + bout[c];
        }
    }
}

// ---------------------------------------------------------------------------
extern "C" void kernel_launch(void* const* d_in, const int* in_sizes, int n_in,
                              void* d_out, int out_size) {
    const float* x    = (const float*)d_in[0];   // (32,256,56,56)
    const float* pos  = (const float*)d_in[1];   // (13,13)
    const float* wqkv = (const float*)d_in[2];   // (256,768)
    const float* wout = (const float*)d_in[3];   // (256,256)
    const float* bout = (const float*)d_in[4];   // (256,)

    float* out      = (float*)d_out;                         // 25,690,112 floats
    float* attn_out = out + (size_t)BATCH * DIM * SP;        // 39,337,984 floats

    dim3 g1(M_TOTAL / 64, QKV_N / 64);
    qkv_gemm<<<g1, 256>>>(x, wqkv);

    attn_kernel<<<BATCH * NWIN * HEADS, 128>>>(pos, attn_out);

    dim3 g3(M_TOTAL / 64, DIM / 64);
    out_gemm<<<g3, 256>>>(wout, bout, out);
}

// round 4
// speedup vs baseline: 1.6668x; 1.6668x over previous
#include <cuda_runtime.h>
#include <cstdint>

#define BATCH 32
#define DIM   256
#define HW    56
#define SP    (HW*HW)        // 3136
#define PW    7
#define PP    49
#define DD    3
#define N1    8
#define N2    8
#define NWIN  64
#define HEADS 8
#define DH    32
#define INNER 256
#define QKV_N 768
#define M_TOTAL (BATCH*NWIN*PP)   // 100352

__device__ float g_qkv[(size_t)M_TOTAL * QKV_N];   // ~308 MB
__device__ float g_att[(size_t)M_TOTAL * INNER];   // ~103 MB

__device__ __forceinline__ int row_to_off(int r) {
    int bi  = r / (NWIN * PP);
    int rem = r % (NWIN * PP);
    int w   = rem / PP;
    int t   = rem % PP;
    int n1i = w / N2, n2i = w % N2;
    int py  = t / PW, px  = t % PW;
    int hh  = (n1i * PW + py + DD) % HW;
    int ww  = (n2i * PW + px + DD) % HW;
    return bi * DIM * SP + hh * HW + ww;
}

// ---------------------------------------------------------------------------
// Kernel 1: qkv = window(roll(x)) @ w_qkv   — 128x128 tile, 8x8 micro-tile
// ---------------------------------------------------------------------------
__global__ void __launch_bounds__(256) qkv_gemm(const float* __restrict__ x,
                                                const float* __restrict__ wqkv) {
    __shared__ float As[16][128];
    __shared__ float Bs[16][128];
    __shared__ int   rowoff[128];

    const int m0  = blockIdx.x * 128;
    const int n0  = blockIdx.y * 128;
    const int tid = threadIdx.x;

    if (tid < 128) rowoff[tid] = row_to_off(m0 + tid);
    __syncthreads();

    const int lm  = tid & 127;     // m/n index for loads (coalesced)
    const int lk0 = tid >> 7;      // 0..1
    const int tr  = (tid >> 4) * 8;
    const int tc  = (tid & 15) * 8;

    float acc[8][8] = {};

    for (int k0 = 0; k0 < DIM; k0 += 16) {
        #pragma unroll
        for (int i = 0; i < 8; i++) {
            int kk = lk0 + 2 * i;
            As[kk][lm] = x[rowoff[lm] + (k0 + kk) * SP];
            Bs[kk][lm] = wqkv[(k0 + kk) * QKV_N + n0 + lm];
        }
        __syncthreads();
        #pragma unroll
        for (int k = 0; k < 16; k++) {
            float a[8], b[8];
            *(float4*)(a)     = *(const float4*)&As[k][tr];
            *(float4*)(a + 4) = *(const float4*)&As[k][tr + 4];
            *(float4*)(b)     = *(const float4*)&Bs[k][tc];
            *(float4*)(b + 4) = *(const float4*)&Bs[k][tc + 4];
            #pragma unroll
            for (int i = 0; i < 8; i++)
                #pragma unroll
                for (int j = 0; j < 8; j++)
                    acc[i][j] += a[i] * b[j];
        }
        __syncthreads();
    }

    #pragma unroll
    for (int i = 0; i < 8; i++) {
        float* dst = &g_qkv[(size_t)(m0 + tr + i) * QKV_N + n0 + tc];
        *(float4*)(dst)     = make_float4(acc[i][0], acc[i][1], acc[i][2], acc[i][3]);
        *(float4*)(dst + 4) = make_float4(acc[i][4], acc[i][5], acc[i][6], acc[i][7]);
    }
}

// ---------------------------------------------------------------------------
// Kernel 2: per (b, window, head) attention. Conflict-free smem layouts.
// ---------------------------------------------------------------------------
__global__ void __launch_bounds__(128) attn_kernel(const float* __restrict__ pos,
                                                   float* __restrict__ attn_out) {
    const int bid  = blockIdx.x;                // bi*NWIN*HEADS + w*HEADS + head
    const int head = bid % HEADS;
    const int bw   = bid / HEADS;
    const int w    = bw % NWIN;
    const int bi   = bw / NWIN;
    const int tid  = threadIdx.x;

    __shared__ float q[PP][DH];       // broadcast reads
    __shared__ float kT[DH][52];      // transposed K: lane-consecutive j -> no conflicts
    __shared__ float v[PP][DH];
    __shared__ float dots[PP][53];    // odd stride -> conflict-free softmax columns
    __shared__ float poss[169];

    const float* base = g_qkv + (size_t)(bi * NWIN + w) * PP * QKV_N + head * DH;
    for (int idx = tid; idx < PP * 8; idx += 128) {
        int t = idx >> 3, c = idx & 7;
        const float* rowp = base + (size_t)t * QKV_N + c * 4;
        float4 qf = *(const float4*)(rowp);
        float4 kf = *(const float4*)(rowp + INNER);
        float4 vf = *(const float4*)(rowp + 2 * INNER);
        *(float4*)&q[t][c * 4] = qf;
        *(float4*)&v[t][c * 4] = vf;
        int d = c * 4;
        kT[d][t] = kf.x; kT[d + 1][t] = kf.y; kT[d + 2][t] = kf.z; kT[d + 3][t] = kf.w;
    }
    if (tid < DH) { kT[tid][49] = 0.f; kT[tid][50] = 0.f; kT[tid][51] = 0.f; }
    for (int idx = tid; idx < 169; idx += 128) poss[idx] = pos[idx];
    __syncthreads();

    const bool m_ul = (w >= NWIN - N2);                                          // 56..63
    const bool m_lr = (w >= NWIN - N1 - 1) && ((w - (NWIN - N1 - 1)) % N1 == 0); // {55,63}
    const float NEG = -1e30f;
    const float scale = 0.17677669529663687f;  // 1/sqrt(32)

    // dots: 49 rows x 13 j-chunks (float4 over j)
    for (int idx = tid; idx < PP * 13; idx += 128) {
        int i = idx / 13, j0 = (idx % 13) * 4;
        float4 s = make_float4(0.f, 0.f, 0.f, 0.f);
        #pragma unroll
        for (int d = 0; d < DH; d++) {
            float qv = q[i][d];
            float4 kf = *(const float4*)&kT[d][j0];
            s.x += qv * kf.x; s.y += qv * kf.y; s.z += qv * kf.z; s.w += qv * kf.w;
        }
        int iy = i / PW, ix = i % PW;
        float sv[4] = {s.x, s.y, s.z, s.w};
        #pragma unroll
        for (int jj = 0; jj < 4; jj++) {
            int j = j0 + jj;
            if (j < PP) {
                int jy = j / PW, jx = j % PW;
                float val = sv[jj] * scale + poss[(jy - iy + 6) * 13 + (jx - ix + 6)];
                if (m_ul && ((iy >= 4) != (jy >= 4))) val = NEG;
                if (m_lr && ((ix >= 4) != (jx >= 4))) val = NEG;
                dots[i][j] = val;
            }
        }
    }
    __syncthreads();

    if (tid < PP) {
        int i = tid;
        float m = -3.4e38f;
        #pragma unroll
        for (int j = 0; j < PP; j++) m = fmaxf(m, dots[i][j]);
        float sum = 0.f;
        #pragma unroll
        for (int j = 0; j < PP; j++) {
            float e = __expf(dots[i][j] - m);
            dots[i][j] = e;
            sum += e;
        }
        float inv = 1.0f / sum;
        #pragma unroll
        for (int j = 0; j < PP; j++) dots[i][j] *= inv;
    }
    __syncthreads();

    float* ao = attn_out + (size_t)bid * (PP * PP);
    for (int idx = tid; idx < PP * PP; idx += 128)
        ao[idx] = dots[idx / PP][idx % PP];

    float* ob = g_att + (size_t)(bi * NWIN + w) * PP * INNER + head * DH;
    for (int idx = tid; idx < PP * DH; idx += 128) {
        int i = idx / DH, d = idx % DH;
        float s = 0.f;
        #pragma unroll
        for (int j = 0; j < PP; j++) s += dots[i][j] * v[j][d];
        ob[(size_t)i * INNER + d] = s;
    }
}

// ---------------------------------------------------------------------------
// Kernel 3: out = g_att @ w_out + b_out, scattered inverse window + roll
// ---------------------------------------------------------------------------
__global__ void __launch_bounds__(256) out_gemm(const float* __restrict__ wout,
                                                const float* __restrict__ bout,
                                                float* __restrict__ out) {
    __shared__ float As[16][128];
    __shared__ float Bs[16][128];
    __shared__ int   rowoff[128];

    const int m0  = blockIdx.x * 128;
    const int n0  = blockIdx.y * 128;
    const int tid = threadIdx.x;

    if (tid < 128) rowoff[tid] = row_to_off(m0 + tid);
    __syncthreads();

    const int lm  = tid & 127;
    const int lk0 = tid >> 7;
    const int tr  = (tid >> 4) * 8;
    const int tc  = (tid & 15) * 8;

    float acc[8][8] = {};

    for (int k0 = 0; k0 < INNER; k0 += 16) {
        #pragma unroll
        for (int i = 0; i < 8; i++) {
            int kk = lk0 + 2 * i;
            As[kk][lm] = g_att[(size_t)(m0 + lm) * INNER + k0 + kk];
            Bs[kk][lm] = wout[(k0 + kk) * DIM + n0 + lm];
        }
        __syncthreads();
        #pragma unroll
        for (int k = 0; k < 16; k++) {
            float a[8], b[8];
            *(float4*)(a)     = *(const float4*)&As[k][tr];
            *(float4*)(a + 4) = *(const float4*)&As[k][tr + 4];
            *(float4*)(b)     = *(const float4*)&Bs[k][tc];
            *(float4*)(b + 4) = *(const float4*)&Bs[k][tc + 4];
            #pragma unroll
            for (int i = 0; i < 8; i++)
                #pragma unroll
                for (int j = 0; j < 8; j++)
                    acc[i][j] += a[i] * b[j];
        }
        __syncthreads();
    }

    #pragma unroll
    for (int i = 0; i < 8; i++) {
        int ro = rowoff[tr + i];
        #pragma unroll
        for (int j = 0; j < 8; j++) {
            int c = n0 + tc + j;
            out[ro + c * SP] = acc[i][j] + bout[c];
        }
    }
}

// ---------------------------------------------------------------------------
extern "C" void kernel_launch(void* const* d_in, const int* in_sizes, int n_in,
                              void* d_out, int out_size) {
    const float* x    = (const float*)d_in[0];
    const float* pos  = (const float*)d_in[1];
    const float* wqkv = (const float*)d_in[2];
    const float* wout = (const float*)d_in[3];
    const float* bout = (const float*)d_in[4];

    float* out      = (float*)d_out;
    float* attn_out = out + (size_t)BATCH * DIM * SP;

    dim3 g1(M_TOTAL / 128, QKV_N / 128);
    qkv_gemm<<<g1, 256>>>(x, wqkv);

    attn_kernel<<<BATCH * NWIN * HEADS, 128>>>(pos, attn_out);

    dim3 g3(M_TOTAL / 128, DIM / 128);
    out_gemm<<<g3, 256>>>(wout, bout, out);
}